// round 2
// baseline (speedup 1.0000x reference)
#include <cuda_runtime.h>
#include <math.h>

#define SEQ   2048
#define HID   1024
#define NHEAD 16
#define DK    64

// Scratch (allocation-free rule: __device__ globals)
__device__ float g_Qh[NHEAD * SEQ * DK];   // [head][s][d]
__device__ float g_Kh[NHEAD * SEQ * DK];
__device__ float g_Vh[NHEAD * SEQ * DK];
__device__ float g_Ob[SEQ * HID];          // attention out, [s][head*64+d]

// ---------------------------------------------------------------------------
// GEMM: C = A @ W^T + bias.  A:[M][1024] row-major, W:[N][1024] row-major.
// Block tile 128x128, K-tile 16, 256 threads, 8x8 per-thread register tile.
// A and W tiles stored k-major-transposed in smem for float4 compute loads.
// ---------------------------------------------------------------------------
template <bool HEADSPLIT>
__device__ __forceinline__ void gemm128(const float* __restrict__ A,
                                        const float* __restrict__ W,
                                        const float* __restrict__ bias,
                                        float* __restrict__ C) {
    __shared__ float At[16][132];   // [k][m], pad 132 (16B-aligned rows)
    __shared__ float Wt[16][132];   // [k][n]

    const int tid = threadIdx.x;
    const int tx  = tid & 15;       // 0..15 -> n
    const int ty  = tid >> 4;       // 0..15 -> m
    const int m0  = blockIdx.x * 128;
    const int n0  = blockIdx.y * 128;

    float acc[8][8];
#pragma unroll
    for (int i = 0; i < 8; i++)
#pragma unroll
        for (int j = 0; j < 8; j++) acc[i][j] = 0.f;

    for (int k0 = 0; k0 < HID; k0 += 16) {
#pragma unroll
        for (int l = 0; l < 2; l++) {
            int fidx = tid + l * 256;        // 512 float4s per operand tile
            int r    = fidx >> 2;            // 0..127
            int c4   = (fidx & 3) * 4;       // 0,4,8,12
            float4 av = *(const float4*)(A + (size_t)(m0 + r) * HID + k0 + c4);
            At[c4 + 0][r] = av.x; At[c4 + 1][r] = av.y;
            At[c4 + 2][r] = av.z; At[c4 + 3][r] = av.w;
            float4 wv = *(const float4*)(W + (size_t)(n0 + r) * HID + k0 + c4);
            Wt[c4 + 0][r] = wv.x; Wt[c4 + 1][r] = wv.y;
            Wt[c4 + 2][r] = wv.z; Wt[c4 + 3][r] = wv.w;
        }
        __syncthreads();
#pragma unroll
        for (int kk = 0; kk < 16; kk++) {
            float a[8], b[8];
            *(float4*)(a)     = *(const float4*)&At[kk][ty * 8];
            *(float4*)(a + 4) = *(const float4*)&At[kk][ty * 8 + 4];
            *(float4*)(b)     = *(const float4*)&Wt[kk][tx * 8];
            *(float4*)(b + 4) = *(const float4*)&Wt[kk][tx * 8 + 4];
#pragma unroll
            for (int i = 0; i < 8; i++)
#pragma unroll
                for (int j = 0; j < 8; j++) acc[i][j] += a[i] * b[j];
        }
        __syncthreads();
    }

#pragma unroll
    for (int i = 0; i < 8; i++) {
        int m = m0 + ty * 8 + i;
#pragma unroll
        for (int j = 0; j < 8; j++) {
            int n   = n0 + tx * 8 + j;
            float v = acc[i][j] + bias[n];
            if (HEADSPLIT)
                C[((size_t)(n >> 6) * SEQ + m) * DK + (n & 63)] = v;
            else
                C[(size_t)m * HID + n] = v;
        }
    }
}

__global__ __launch_bounds__(256) void qkv_gemm(
    const float* __restrict__ q, const float* __restrict__ k, const float* __restrict__ v,
    const float* __restrict__ Wq, const float* __restrict__ bq,
    const float* __restrict__ Wk, const float* __restrict__ bk,
    const float* __restrict__ Wv, const float* __restrict__ bv) {
    const float *A, *W, *b;
    float* C;
    if (blockIdx.z == 0)      { A = q; W = Wq; b = bq; C = g_Qh; }
    else if (blockIdx.z == 1) { A = k; W = Wk; b = bk; C = g_Kh; }
    else                      { A = v; W = Wv; b = bv; C = g_Vh; }
    gemm128<true>(A, W, b, C);
}

__global__ __launch_bounds__(256) void out_gemm(
    const float* __restrict__ Wo, const float* __restrict__ bo,
    float* __restrict__ out) {
    gemm128<false>(g_Ob, Wo, bo, out);
}

// ---------------------------------------------------------------------------
// Flash-style attention per (q-block, head). BM=BN=64, 256 threads (16x16),
// 4x4 micro-tile per thread. d_k = 64.
// Quirk preserved: masked scores are the literal value 0.0 inside softmax.
// Smem: Qt[d][r], KPt (K as [d][c], reused as P [c][r]), Vs[c][d]. 48KB static.
// ---------------------------------------------------------------------------
__global__ __launch_bounds__(256) void attn_kernel(const int* __restrict__ mask) {
    __shared__ float Qt[64][64];    // [d][row]
    __shared__ float KPt[64][64];   // K: [d][col]  ->  P: [col][row]
    __shared__ float Vs[64][64];    // [col][d]

    const int tid  = threadIdx.x;
    const int tx   = tid & 15;
    const int ty   = tid >> 4;
    const int head = blockIdx.y;
    const int q0   = blockIdx.x * 64;
    const int row0 = ty * 4;
    const int col0 = tx * 4;

    const float* Qp = g_Qh + ((size_t)head * SEQ + q0) * DK;
    const float* Kp = g_Kh + (size_t)head * SEQ * DK;
    const float* Vp = g_Vh + (size_t)head * SEQ * DK;

    // Load Q tile (transposed store; one-time cost)
#pragma unroll
    for (int l = 0; l < 4; l++) {
        int idx = tid + l * 256;        // 1024 float4s? no: 64*16 = 1024 float4-slots
        int r   = idx >> 4;             // 0..63
        int c4  = (idx & 15) * 4;       // 0..60
        float4 v = *(const float4*)(Qp + r * DK + c4);
        Qt[c4 + 0][r] = v.x; Qt[c4 + 1][r] = v.y;
        Qt[c4 + 2][r] = v.z; Qt[c4 + 3][r] = v.w;
    }

    float Oacc[4][4];
    float mrow[4], lrow[4];
#pragma unroll
    for (int i = 0; i < 4; i++) {
        mrow[i] = -1e30f;
        lrow[i] = 0.f;
#pragma unroll
        for (int j = 0; j < 4; j++) Oacc[i][j] = 0.f;
    }

    for (int kb = 0; kb < SEQ / 64; kb++) {
        __syncthreads();   // previous iter's P/V reads done before overwrite
        // Load K (transposed) and V (natural) tiles
#pragma unroll
        for (int l = 0; l < 4; l++) {
            int idx = tid + l * 256;
            int r   = idx >> 4;
            int c4  = (idx & 15) * 4;
            float4 kv = *(const float4*)(Kp + (size_t)(kb * 64 + r) * DK + c4);
            KPt[c4 + 0][r] = kv.x; KPt[c4 + 1][r] = kv.y;
            KPt[c4 + 2][r] = kv.z; KPt[c4 + 3][r] = kv.w;
            float4 vv = *(const float4*)(Vp + (size_t)(kb * 64 + r) * DK + c4);
            *(float4*)(&Vs[r][c4]) = vv;
        }
        __syncthreads();

        // Scores: s = Q @ K^T
        float s[4][4];
#pragma unroll
        for (int i = 0; i < 4; i++)
#pragma unroll
            for (int j = 0; j < 4; j++) s[i][j] = 0.f;
#pragma unroll 8
        for (int d = 0; d < 64; d++) {
            float4 qa = *(const float4*)(&Qt[d][row0]);
            float4 ka = *(const float4*)(&KPt[d][col0]);
            float a[4] = {qa.x, qa.y, qa.z, qa.w};
            float b[4] = {ka.x, ka.y, ka.z, ka.w};
#pragma unroll
            for (int i = 0; i < 4; i++)
#pragma unroll
                for (int j = 0; j < 4; j++) s[i][j] += a[i] * b[j];
        }

        // Scale + mask quirk (masked -> literal 0.0)
#pragma unroll
        for (int i = 0; i < 4; i++) {
            const int4 mv = *(const int4*)(mask + (size_t)(q0 + row0 + i) * SEQ + kb * 64 + col0);
            s[i][0] = mv.x ? s[i][0] * 0.125f : 0.f;
            s[i][1] = mv.y ? s[i][1] * 0.125f : 0.f;
            s[i][2] = mv.z ? s[i][2] * 0.125f : 0.f;
            s[i][3] = mv.w ? s[i][3] * 0.125f : 0.f;
        }

        // Online softmax (row state replicated across the 16 tx lanes)
        float p[4][4], corr[4];
#pragma unroll
        for (int i = 0; i < 4; i++) {
            float mx = fmaxf(fmaxf(s[i][0], s[i][1]), fmaxf(s[i][2], s[i][3]));
            mx = fmaxf(mx, __shfl_xor_sync(0xffffffffu, mx, 1, 16));
            mx = fmaxf(mx, __shfl_xor_sync(0xffffffffu, mx, 2, 16));
            mx = fmaxf(mx, __shfl_xor_sync(0xffffffffu, mx, 4, 16));
            mx = fmaxf(mx, __shfl_xor_sync(0xffffffffu, mx, 8, 16));
            float mnew = fmaxf(mrow[i], mx);
            float ps = 0.f;
#pragma unroll
            for (int j = 0; j < 4; j++) { p[i][j] = __expf(s[i][j] - mnew); ps += p[i][j]; }
            ps += __shfl_xor_sync(0xffffffffu, ps, 1, 16);
            ps += __shfl_xor_sync(0xffffffffu, ps, 2, 16);
            ps += __shfl_xor_sync(0xffffffffu, ps, 4, 16);
            ps += __shfl_xor_sync(0xffffffffu, ps, 8, 16);
            corr[i] = __expf(mrow[i] - mnew);
            lrow[i] = lrow[i] * corr[i] + ps;
            mrow[i] = mnew;
        }

        __syncthreads();   // everyone done reading KPt as K
        // Write P transposed: P[col][row]
#pragma unroll
        for (int i = 0; i < 4; i++)
#pragma unroll
            for (int j = 0; j < 4; j++)
                KPt[col0 + j][row0 + i] = p[i][j];
        // Rescale O
#pragma unroll
        for (int i = 0; i < 4; i++)
#pragma unroll
            for (int j = 0; j < 4; j++) Oacc[i][j] *= corr[i];
        __syncthreads();

        // O += P @ V
#pragma unroll 8
        for (int c = 0; c < 64; c++) {
            float4 pv = *(const float4*)(&KPt[c][row0]);
            float4 vv = *(const float4*)(&Vs[c][col0]);
            float pp[4] = {pv.x, pv.y, pv.z, pv.w};
            float vb[4] = {vv.x, vv.y, vv.z, vv.w};
#pragma unroll
            for (int i = 0; i < 4; i++)
#pragma unroll
                for (int j = 0; j < 4; j++) Oacc[i][j] += pp[i] * vb[j];
        }
    }

    // Epilogue: normalize and write to [s][head*64+d]
#pragma unroll
    for (int i = 0; i < 4; i++) {
        float inv = 1.f / lrow[i];
        int q = q0 + row0 + i;
        float4 o;
        o.x = Oacc[i][0] * inv;
        o.y = Oacc[i][1] * inv;
        o.z = Oacc[i][2] * inv;
        o.w = Oacc[i][3] * inv;
        *(float4*)(g_Ob + (size_t)q * HID + head * DK + col0) = o;
    }
}

// ---------------------------------------------------------------------------
extern "C" void kernel_launch(void* const* d_in, const int* in_sizes, int n_in,
                              void* d_out, int out_size) {
    const float* q    = (const float*)d_in[0];
    const float* k    = (const float*)d_in[1];
    const float* v    = (const float*)d_in[2];
    const int*   mask = (const int*)  d_in[3];
    const float* Wq   = (const float*)d_in[4];
    const float* bq   = (const float*)d_in[5];
    const float* Wk   = (const float*)d_in[6];
    const float* bk   = (const float*)d_in[7];
    const float* Wv   = (const float*)d_in[8];
    const float* bv   = (const float*)d_in[9];
    const float* Wo   = (const float*)d_in[10];
    const float* bo   = (const float*)d_in[11];
    float* out = (float*)d_out;

    qkv_gemm<<<dim3(SEQ / 128, HID / 128, 3), 256>>>(q, k, v, Wq, bq, Wk, bk, Wv, bv);
    attn_kernel<<<dim3(SEQ / 64, NHEAD), 256>>>(mask);
    out_gemm<<<dim3(SEQ / 128, HID / 128), 256>>>(Wo, bo, out);
}

// round 6
// speedup vs baseline: 2.7512x; 2.7512x over previous
#include <cuda_runtime.h>
#include <cuda_bf16.h>
#include <math.h>
#include <stdint.h>

#define SEQ   2048
#define HID   1024
#define NHEAD 16
#define DK    64

// __device__ scratch (allocation-free rule)
__device__ __nv_bfloat16 g_Qhh[NHEAD * SEQ * DK];
__device__ __nv_bfloat16 g_Qll[NHEAD * SEQ * DK];
__device__ __nv_bfloat16 g_Khh[NHEAD * SEQ * DK];
__device__ __nv_bfloat16 g_Kll[NHEAD * SEQ * DK];
__device__ __nv_bfloat16 g_Vhh[NHEAD * SEQ * DK];
__device__ __nv_bfloat16 g_Vll[NHEAD * SEQ * DK];
__device__ float    g_Ob[SEQ * HID];
__device__ uint32_t g_mbits[SEQ * (SEQ / 32)];

// ---------------------------------------------------------------------------
// helpers
// ---------------------------------------------------------------------------
__device__ __forceinline__ uint32_t smem_u32(const void* p) {
    uint32_t r;
    asm("{ .reg .u64 t; cvta.to.shared.u64 t, %1; cvt.u32.u64 %0, t; }"
        : "=r"(r) : "l"(p));
    return r;
}

__device__ __forceinline__ void ldsm_x4(uint32_t r[4], uint32_t addr) {
    asm volatile("ldmatrix.sync.aligned.m8n8.x4.shared.b16 {%0,%1,%2,%3}, [%4];"
                 : "=r"(r[0]), "=r"(r[1]), "=r"(r[2]), "=r"(r[3]) : "r"(addr));
}
__device__ __forceinline__ void ldsm_x2(uint32_t r[2], uint32_t addr) {
    asm volatile("ldmatrix.sync.aligned.m8n8.x2.shared.b16 {%0,%1}, [%2];"
                 : "=r"(r[0]), "=r"(r[1]) : "r"(addr));
}
__device__ __forceinline__ void ldsm_x2t(uint32_t r[2], uint32_t addr) {
    asm volatile("ldmatrix.sync.aligned.m8n8.x2.trans.shared.b16 {%0,%1}, [%2];"
                 : "=r"(r[0]), "=r"(r[1]) : "r"(addr));
}
__device__ __forceinline__ void mma_bf16(float d[4], const uint32_t a[4],
                                         const uint32_t b[2]) {
    asm volatile(
        "mma.sync.aligned.m16n8k16.row.col.f32.bf16.bf16.f32 "
        "{%0,%1,%2,%3}, {%4,%5,%6,%7}, {%8,%9}, {%0,%1,%2,%3};"
        : "+f"(d[0]), "+f"(d[1]), "+f"(d[2]), "+f"(d[3])
        : "r"(a[0]), "r"(a[1]), "r"(a[2]), "r"(a[3]), "r"(b[0]), "r"(b[1]));
}
// pack bf16x2: low half = x, high half = y
__device__ __forceinline__ uint32_t pk(float x, float y) {
    uint32_t r;
    asm("cvt.rn.bf16x2.f32 %0, %1, %2;" : "=r"(r) : "f"(y), "f"(x));
    return r;
}
__device__ __forceinline__ float bf_hi_f(float x) {
    return __bfloat162float(__float2bfloat16(x));
}

// ---------------------------------------------------------------------------
// mask bit-pack: mask[q][k] int32 -> g_mbits[q][k/32]
// ---------------------------------------------------------------------------
__global__ __launch_bounds__(256) void pack_mask(const int* __restrict__ mask) {
    int widx = blockIdx.x * 256 + threadIdx.x;     // 2048*64 words
    int q = widx >> 6;
    int w = widx & 63;
    const int4* p = (const int4*)(mask + (size_t)q * SEQ + w * 32);
    uint32_t bits = 0;
#pragma unroll
    for (int i = 0; i < 8; i++) {
        int4 m = p[i];
        bits |= (m.x != 0 ? 1u : 0u) << (4 * i + 0);
        bits |= (m.y != 0 ? 1u : 0u) << (4 * i + 1);
        bits |= (m.z != 0 ? 1u : 0u) << (4 * i + 2);
        bits |= (m.w != 0 ? 1u : 0u) << (4 * i + 3);
    }
    g_mbits[widx] = bits;
}

// ---------------------------------------------------------------------------
// GEMM via mma.sync bf16 split: C = A @ W^T + bias
// extended K = 3072: variants [Ah,Al,Ah] x [Bh,Bh,Bl]
// CTA 128x128, BK=32, 8 warps (2m x 4n), warp tile 64x32.
// MODE 0: write bf16 hi/lo head-split. MODE 1: write fp32 flat.
// ---------------------------------------------------------------------------
#define SROW 40    // bf16 per smem row (32 used + 8 pad) -> 80B stride

template <int MODE>
__device__ __forceinline__ void gemm_body(const float* __restrict__ A,
                                          const float* __restrict__ W,
                                          const float* __restrict__ bias,
                                          float* __restrict__ Cf,
                                          __nv_bfloat16* __restrict__ Chi,
                                          __nv_bfloat16* __restrict__ Clo) {
    __shared__ __nv_bfloat16 sA[128 * SROW];
    __shared__ __nv_bfloat16 sB[128 * SROW];

    const int tid  = threadIdx.x;
    const int lane = tid & 31;
    const int w    = tid >> 5;
    const int wm   = w >> 2;          // 0..1
    const int wn   = w & 3;           // 0..3
    const int m0   = blockIdx.x * 128;
    const int n0   = blockIdx.y * 128;
    const uint32_t sAb = smem_u32(sA);
    const uint32_t sBb = smem_u32(sB);

    float acc[4][4][4];
#pragma unroll
    for (int i = 0; i < 4; i++)
#pragma unroll
        for (int j = 0; j < 4; j++)
#pragma unroll
            for (int e = 0; e < 4; e++) acc[i][j][e] = 0.f;

    float4 ar[4], br[4];

    auto load_t = [&](int t) {
        const int kfp = (t & 31) * 32;
#pragma unroll
        for (int q = 0; q < 4; q++) {
            int idx = tid + q * 256;
            int r   = idx >> 3;
            int c4  = (idx & 7) * 4;
            ar[q] = *(const float4*)(A + (size_t)(m0 + r) * HID + kfp + c4);
            br[q] = *(const float4*)(W + (size_t)(n0 + r) * HID + kfp + c4);
        }
    };
    auto cv = [](float x, bool lov) -> float {
        return lov ? (x - bf_hi_f(x)) : x;
    };
    auto store_t = [&](int t) {
        const bool alov = ((t >> 5) == 1);
        const bool blov = ((t >> 5) == 2);
#pragma unroll
        for (int q = 0; q < 4; q++) {
            int idx = tid + q * 256;
            int r   = idx >> 3;
            int c4  = (idx & 7) * 4;
            uint2 pa, pb;
            pa.x = pk(cv(ar[q].x, alov), cv(ar[q].y, alov));
            pa.y = pk(cv(ar[q].z, alov), cv(ar[q].w, alov));
            pb.x = pk(cv(br[q].x, blov), cv(br[q].y, blov));
            pb.y = pk(cv(br[q].z, blov), cv(br[q].w, blov));
            *(uint2*)(sA + r * SROW + c4) = pa;
            *(uint2*)(sB + r * SROW + c4) = pb;
        }
    };

    load_t(0);
    const int NT = 96;   // 3072 / 32
    for (int t = 0; t < NT; t++) {
        store_t(t);
        __syncthreads();
        if (t + 1 < NT) load_t(t + 1);
        uint32_t afr[4][4], bfr[4][2];
#pragma unroll
        for (int kk = 0; kk < 2; kk++) {
#pragma unroll
            for (int i = 0; i < 4; i++)
                ldsm_x4(afr[i], sAb + 2u * ((wm * 64 + 16 * i + (lane & 15)) * SROW
                                            + kk * 16 + ((lane >> 4) & 1) * 8));
#pragma unroll
            for (int j = 0; j < 4; j++)
                ldsm_x2(bfr[j], sBb + 2u * ((wn * 32 + 8 * j + (lane & 7)) * SROW
                                            + kk * 16 + ((lane >> 3) & 1) * 8));
#pragma unroll
            for (int i = 0; i < 4; i++)
#pragma unroll
                for (int j = 0; j < 4; j++) mma_bf16(acc[i][j], afr[i], bfr[j]);
        }
        __syncthreads();
    }

    // epilogue
#pragma unroll
    for (int j = 0; j < 4; j++) {
        const int gn0 = n0 + wn * 32 + 8 * j + 2 * (lane & 3);
        const float b0 = __ldg(bias + gn0);
        const float b1 = __ldg(bias + gn0 + 1);
#pragma unroll
        for (int i = 0; i < 4; i++) {
            const int r0 = m0 + wm * 64 + 16 * i + (lane >> 2);
            const int r1 = r0 + 8;
            float c0 = acc[i][j][0] + b0, c1 = acc[i][j][1] + b1;
            float c2 = acc[i][j][2] + b0, c3 = acc[i][j][3] + b1;
            if (MODE == 1) {
                *(float2*)(Cf + (size_t)r0 * HID + gn0) = make_float2(c0, c1);
                *(float2*)(Cf + (size_t)r1 * HID + gn0) = make_float2(c2, c3);
            } else {
                const int head = gn0 >> 6;
                const int d    = gn0 & 63;
                size_t i0 = ((size_t)head * SEQ + r0) * DK + d;
                size_t i1 = ((size_t)head * SEQ + r1) * DK + d;
                *(uint32_t*)(Chi + i0) = pk(bf_hi_f(c0), bf_hi_f(c1));
                *(uint32_t*)(Clo + i0) = pk(c0 - bf_hi_f(c0), c1 - bf_hi_f(c1));
                *(uint32_t*)(Chi + i1) = pk(bf_hi_f(c2), bf_hi_f(c3));
                *(uint32_t*)(Clo + i1) = pk(c2 - bf_hi_f(c2), c3 - bf_hi_f(c3));
            }
        }
    }
}

__global__ __launch_bounds__(256) void qkv_gemm(
    const float* __restrict__ q, const float* __restrict__ k, const float* __restrict__ v,
    const float* __restrict__ Wq, const float* __restrict__ bq,
    const float* __restrict__ Wk, const float* __restrict__ bk,
    const float* __restrict__ Wv, const float* __restrict__ bv) {
    const float *A, *W, *b;
    __nv_bfloat16 *Ch, *Cl;
    if (blockIdx.z == 0)      { A = q; W = Wq; b = bq; Ch = g_Qhh; Cl = g_Qll; }
    else if (blockIdx.z == 1) { A = k; W = Wk; b = bk; Ch = g_Khh; Cl = g_Kll; }
    else                      { A = v; W = Wv; b = bv; Ch = g_Vhh; Cl = g_Vll; }
    gemm_body<0>(A, W, b, nullptr, Ch, Cl);
}

__global__ __launch_bounds__(256) void out_gemm(
    const float* __restrict__ Wo, const float* __restrict__ bo,
    float* __restrict__ out) {
    gemm_body<1>(g_Ob, Wo, bo, out, nullptr, nullptr);
}

// ---------------------------------------------------------------------------
// Attention: per (128 q-rows, head) CTA. 8 warps x 16 q-rows. Keyblock 128.
// QK^T and P.V via mma.sync bf16 with hi/lo split. Mask quirk: score -> 0.
// ---------------------------------------------------------------------------
#define AROW 72                       // bf16 per smem row (64 + 8 pad) -> 144B
#define ATILE (128 * AROW)            // bf16 elems per tile
#define ASMEM_BYTES (6 * ATILE * 2)   // Qh Ql Kh Kl Vh Vl = 110592 B

__global__ __launch_bounds__(256) void attn_kernel() {
    extern __shared__ __nv_bfloat16 sm[];
    __nv_bfloat16* sQh = sm;
    __nv_bfloat16* sQl = sm + ATILE;
    __nv_bfloat16* sKh = sm + 2 * ATILE;
    __nv_bfloat16* sKl = sm + 3 * ATILE;
    __nv_bfloat16* sVh = sm + 4 * ATILE;
    __nv_bfloat16* sVl = sm + 5 * ATILE;

    const int tid  = threadIdx.x;
    const int lane = tid & 31;
    const int w    = tid >> 5;
    const int head = blockIdx.y;
    const int q0   = blockIdx.x * 128;

    const uint32_t bQh = smem_u32(sQh), bQl = smem_u32(sQl);
    const uint32_t bKh = smem_u32(sKh), bKl = smem_u32(sKl);
    const uint32_t bVh = smem_u32(sVh), bVl = smem_u32(sVl);

    const size_t hbase = (size_t)head * SEQ * DK;

    // load Q tile (hi, lo): 128 rows x 64 cols, uint4 = 8 bf16 -> 1024 stores/tile
#pragma unroll
    for (int q = 0; q < 4; q++) {
        int idx = tid + q * 256;        // 0..1023
        int r   = idx >> 3;             // 0..127
        int cc  = (idx & 7) * 8;        // 0..56
        *(uint4*)(sQh + r * AROW + cc) = *(const uint4*)(g_Qhh + hbase + (size_t)(q0 + r) * DK + cc);
        *(uint4*)(sQl + r * AROW + cc) = *(const uint4*)(g_Qll + hbase + (size_t)(q0 + r) * DK + cc);
    }

    float oacc[8][4];
#pragma unroll
    for (int j = 0; j < 8; j++)
#pragma unroll
        for (int e = 0; e < 4; e++) oacc[j][e] = 0.f;
    float mrow[2] = {-1e30f, -1e30f};
    float lrow[2] = {0.f, 0.f};

    const int row0g = q0 + 16 * w + (lane >> 2);
    const int row1g = row0g + 8;

    for (int kb = 0; kb < SEQ / 128; kb++) {
        __syncthreads();
#pragma unroll
        for (int q = 0; q < 4; q++) {
            int idx = tid + q * 256;    // 0..1023
            int r   = idx >> 3;         // 0..127
            int cc  = (idx & 7) * 8;    // 0..56
            size_t g = hbase + (size_t)(kb * 128 + r) * DK + cc;
            *(uint4*)(sKh + r * AROW + cc) = *(const uint4*)(g_Khh + g);
            *(uint4*)(sKl + r * AROW + cc) = *(const uint4*)(g_Kll + g);
            *(uint4*)(sVh + r * AROW + cc) = *(const uint4*)(g_Vhh + g);
            *(uint4*)(sVl + r * AROW + cc) = *(const uint4*)(g_Vll + g);
        }
        __syncthreads();

        // ---- S = Q K^T (split) ----
        float sacc[16][4];
#pragma unroll
        for (int j = 0; j < 16; j++)
#pragma unroll
            for (int e = 0; e < 4; e++) sacc[j][e] = 0.f;

        const uint32_t a_off = 2u * ((16 * w + (lane & 15)) * AROW + ((lane >> 4) & 1) * 8);
        const uint32_t b_roff = 2u * ((lane & 7) * AROW + ((lane >> 3) & 1) * 8);

#pragma unroll
        for (int kk = 0; kk < 4; kk++) {
            uint32_t qh[4], ql[4];
            ldsm_x4(qh, bQh + a_off + 2u * kk * 16);
            ldsm_x4(ql, bQl + a_off + 2u * kk * 16);
#pragma unroll
            for (int j = 0; j < 16; j++) {
                uint32_t kf[2];
                ldsm_x2(kf, bKh + b_roff + 2u * (8 * j * AROW + kk * 16));
                mma_bf16(sacc[j], qh, kf);
                mma_bf16(sacc[j], ql, kf);
            }
#pragma unroll
            for (int j = 0; j < 16; j++) {
                uint32_t kf[2];
                ldsm_x2(kf, bKl + b_roff + 2u * (8 * j * AROW + kk * 16));
                mma_bf16(sacc[j], qh, kf);
            }
        }

        // ---- mask (quirk: masked -> literal 0.0) + scale ----
        uint32_t mw0[4], mw1[4];
#pragma unroll
        for (int i = 0; i < 4; i++) {
            mw0[i] = g_mbits[(size_t)row0g * 64 + kb * 4 + i];
            mw1[i] = g_mbits[(size_t)row1g * 64 + kb * 4 + i];
        }
#pragma unroll
        for (int j = 0; j < 16; j++) {
            int kl = 8 * j + 2 * (lane & 3);
            uint32_t w0 = mw0[kl >> 5], w1 = mw1[kl >> 5];
            int b = kl & 31;
            sacc[j][0] = ((w0 >> b) & 1)       ? sacc[j][0] * 0.125f : 0.f;
            sacc[j][1] = ((w0 >> (b + 1)) & 1) ? sacc[j][1] * 0.125f : 0.f;
            sacc[j][2] = ((w1 >> b) & 1)       ? sacc[j][2] * 0.125f : 0.f;
            sacc[j][3] = ((w1 >> (b + 1)) & 1) ? sacc[j][3] * 0.125f : 0.f;
        }

        // ---- online softmax (rows r0, r0+8) ----
        float mx0 = -1e30f, mx1 = -1e30f;
#pragma unroll
        for (int j = 0; j < 16; j++) {
            mx0 = fmaxf(mx0, fmaxf(sacc[j][0], sacc[j][1]));
            mx1 = fmaxf(mx1, fmaxf(sacc[j][2], sacc[j][3]));
        }
        mx0 = fmaxf(mx0, __shfl_xor_sync(0xffffffffu, mx0, 1, 4));
        mx0 = fmaxf(mx0, __shfl_xor_sync(0xffffffffu, mx0, 2, 4));
        mx1 = fmaxf(mx1, __shfl_xor_sync(0xffffffffu, mx1, 1, 4));
        mx1 = fmaxf(mx1, __shfl_xor_sync(0xffffffffu, mx1, 2, 4));
        const float mn0 = fmaxf(mrow[0], mx0);
        const float mn1 = fmaxf(mrow[1], mx1);
        float s0 = 0.f, s1 = 0.f;
#pragma unroll
        for (int j = 0; j < 16; j++) {
            sacc[j][0] = __expf(sacc[j][0] - mn0); s0 += sacc[j][0];
            sacc[j][1] = __expf(sacc[j][1] - mn0); s0 += sacc[j][1];
            sacc[j][2] = __expf(sacc[j][2] - mn1); s1 += sacc[j][2];
            sacc[j][3] = __expf(sacc[j][3] - mn1); s1 += sacc[j][3];
        }
        s0 += __shfl_xor_sync(0xffffffffu, s0, 1, 4);
        s0 += __shfl_xor_sync(0xffffffffu, s0, 2, 4);
        s1 += __shfl_xor_sync(0xffffffffu, s1, 1, 4);
        s1 += __shfl_xor_sync(0xffffffffu, s1, 2, 4);
        const float c0 = __expf(mrow[0] - mn0);
        const float c1 = __expf(mrow[1] - mn1);
        lrow[0] = lrow[0] * c0 + s0; mrow[0] = mn0;
        lrow[1] = lrow[1] * c1 + s1; mrow[1] = mn1;
#pragma unroll
        for (int j = 0; j < 8; j++) {
            oacc[j][0] *= c0; oacc[j][1] *= c0;
            oacc[j][2] *= c1; oacc[j][3] *= c1;
        }

        // ---- O += P V (split; P straight from registers) ----
        const uint32_t v_coff = 2u * ((lane & 15) * AROW);
#pragma unroll
        for (int kk = 0; kk < 8; kk++) {
            uint32_t ah[4], al[4];
            float p00 = sacc[2 * kk][0],     p01 = sacc[2 * kk][1];
            float p02 = sacc[2 * kk][2],     p03 = sacc[2 * kk][3];
            float p10 = sacc[2 * kk + 1][0], p11 = sacc[2 * kk + 1][1];
            float p12 = sacc[2 * kk + 1][2], p13 = sacc[2 * kk + 1][3];
            ah[0] = pk(p00, p01); ah[1] = pk(p02, p03);
            ah[2] = pk(p10, p11); ah[3] = pk(p12, p13);
            al[0] = pk(p00 - bf_hi_f(p00), p01 - bf_hi_f(p01));
            al[1] = pk(p02 - bf_hi_f(p02), p03 - bf_hi_f(p03));
            al[2] = pk(p10 - bf_hi_f(p10), p11 - bf_hi_f(p11));
            al[3] = pk(p12 - bf_hi_f(p12), p13 - bf_hi_f(p13));
            const uint32_t vrow = 2u * (16 * kk * AROW) + v_coff;
#pragma unroll
            for (int j = 0; j < 8; j++) {
                uint32_t vf[2];
                ldsm_x2t(vf, bVh + vrow + 2u * (j * 8));
                mma_bf16(oacc[j], ah, vf);
                mma_bf16(oacc[j], al, vf);
            }
#pragma unroll
            for (int j = 0; j < 8; j++) {
                uint32_t vf[2];
                ldsm_x2t(vf, bVl + vrow + 2u * (j * 8));
                mma_bf16(oacc[j], ah, vf);
            }
        }
    }

    // epilogue: normalize, write [s][head*64+d] fp32
    const float inv0 = 1.f / lrow[0];
    const float inv1 = 1.f / lrow[1];
#pragma unroll
    for (int j = 0; j < 8; j++) {
        const int col = head * DK + 8 * j + 2 * (lane & 3);
        *(float2*)(g_Ob + (size_t)row0g * HID + col) =
            make_float2(oacc[j][0] * inv0, oacc[j][1] * inv0);
        *(float2*)(g_Ob + (size_t)row1g * HID + col) =
            make_float2(oacc[j][2] * inv1, oacc[j][3] * inv1);
    }
}

// ---------------------------------------------------------------------------
extern "C" void kernel_launch(void* const* d_in, const int* in_sizes, int n_in,
                              void* d_out, int out_size) {
    const float* q    = (const float*)d_in[0];
    const float* k    = (const float*)d_in[1];
    const float* v    = (const float*)d_in[2];
    const int*   mask = (const int*)  d_in[3];
    const float* Wq   = (const float*)d_in[4];
    const float* bq   = (const float*)d_in[5];
    const float* Wk   = (const float*)d_in[6];
    const float* bk   = (const float*)d_in[7];
    const float* Wv   = (const float*)d_in[8];
    const float* bv   = (const float*)d_in[9];
    const float* Wo   = (const float*)d_in[10];
    const float* bo   = (const float*)d_in[11];
    float* out = (float*)d_out;

    static bool attr_set = false;
    if (!attr_set) {
        cudaFuncSetAttribute(attn_kernel, cudaFuncAttributeMaxDynamicSharedMemorySize,
                             ASMEM_BYTES);
        attr_set = true;
    }

    pack_mask<<<SEQ * (SEQ / 32) / 256, 256>>>(mask);
    qkv_gemm<<<dim3(SEQ / 128, HID / 128, 3), 256>>>(q, k, v, Wq, bq, Wk, bk, Wv, bv);
    attn_kernel<<<dim3(SEQ / 128, NHEAD), 256, ASMEM_BYTES>>>();
    out_gemm<<<dim3(SEQ / 128, HID / 128), 256>>>(Wo, bo, out);
}

// round 8
// speedup vs baseline: 2.9867x; 1.0856x over previous
#include <cuda_runtime.h>
#include <cuda_bf16.h>
#include <math.h>
#include <stdint.h>

#define SEQ   2048
#define HID   1024
#define NHEAD 16
#define DK    64

// __device__ scratch (allocation-free rule)
__device__ __nv_bfloat16 g_Xh[3 * SEQ * HID];   // q,k,v inputs hi
__device__ __nv_bfloat16 g_Xl[3 * SEQ * HID];   // q,k,v inputs lo
__device__ __nv_bfloat16 g_Wh[4 * HID * HID];   // Wq,Wk,Wv,Wo hi
__device__ __nv_bfloat16 g_Wl[4 * HID * HID];   // lo
__device__ __nv_bfloat16 g_Qhh[NHEAD * SEQ * DK];
__device__ __nv_bfloat16 g_Qll[NHEAD * SEQ * DK];
__device__ __nv_bfloat16 g_Khh[NHEAD * SEQ * DK];
__device__ __nv_bfloat16 g_Kll[NHEAD * SEQ * DK];
__device__ __nv_bfloat16 g_Vhh[NHEAD * SEQ * DK];
__device__ __nv_bfloat16 g_Vll[NHEAD * SEQ * DK];
__device__ __nv_bfloat16 g_Obh[SEQ * HID];
__device__ __nv_bfloat16 g_Obl[SEQ * HID];
__device__ uint32_t g_mbits[SEQ * (SEQ / 32)];

// ---------------------------------------------------------------------------
// helpers
// ---------------------------------------------------------------------------
__device__ __forceinline__ uint32_t smem_u32(const void* p) {
    uint32_t r;
    asm("{ .reg .u64 t; cvta.to.shared.u64 t, %1; cvt.u32.u64 %0, t; }"
        : "=r"(r) : "l"(p));
    return r;
}
__device__ __forceinline__ void ldsm_x4(uint32_t r[4], uint32_t addr) {
    asm volatile("ldmatrix.sync.aligned.m8n8.x4.shared.b16 {%0,%1,%2,%3}, [%4];"
                 : "=r"(r[0]), "=r"(r[1]), "=r"(r[2]), "=r"(r[3]) : "r"(addr));
}
__device__ __forceinline__ void ldsm_x2(uint32_t r[2], uint32_t addr) {
    asm volatile("ldmatrix.sync.aligned.m8n8.x2.shared.b16 {%0,%1}, [%2];"
                 : "=r"(r[0]), "=r"(r[1]) : "r"(addr));
}
__device__ __forceinline__ void ldsm_x2t(uint32_t r[2], uint32_t addr) {
    asm volatile("ldmatrix.sync.aligned.m8n8.x2.trans.shared.b16 {%0,%1}, [%2];"
                 : "=r"(r[0]), "=r"(r[1]) : "r"(addr));
}
__device__ __forceinline__ void mma_bf16(float d[4], const uint32_t a[4],
                                         const uint32_t b[2]) {
    asm volatile(
        "mma.sync.aligned.m16n8k16.row.col.f32.bf16.bf16.f32 "
        "{%0,%1,%2,%3}, {%4,%5,%6,%7}, {%8,%9}, {%0,%1,%2,%3};"
        : "+f"(d[0]), "+f"(d[1]), "+f"(d[2]), "+f"(d[3])
        : "r"(a[0]), "r"(a[1]), "r"(a[2]), "r"(a[3]), "r"(b[0]), "r"(b[1]));
}
__device__ __forceinline__ uint32_t pk(float x, float y) {
    uint32_t r;
    asm("cvt.rn.bf16x2.f32 %0, %1, %2;" : "=r"(r) : "f"(y), "f"(x));
    return r;
}
__device__ __forceinline__ float bf_hi_f(float x) {
    return __bfloat162float(__float2bfloat16(x));
}
__device__ __forceinline__ void cp16(uint32_t saddr, const void* gaddr) {
    asm volatile("cp.async.cg.shared.global [%0], [%1], 16;"
                 :: "r"(saddr), "l"(gaddr) : "memory");
}
#define CP_COMMIT() asm volatile("cp.async.commit_group;" ::: "memory")
#define CP_WAIT2()  asm volatile("cp.async.wait_group 2;" ::: "memory")

// ---------------------------------------------------------------------------
// hi/lo split conversion: x -> bf16(x), bf16(x - bf16(x))
// ---------------------------------------------------------------------------
__global__ __launch_bounds__(256) void cvt_inputs(const float* __restrict__ q,
                                                  const float* __restrict__ k,
                                                  const float* __restrict__ v) {
    const int z = blockIdx.y;
    const float* src = (z == 0) ? q : (z == 1) ? k : v;
    __nv_bfloat16* dh = g_Xh + (size_t)z * SEQ * HID;
    __nv_bfloat16* dl = g_Xl + (size_t)z * SEQ * HID;
    const int idx = blockIdx.x * 256 + threadIdx.x;
    float4 x = ((const float4*)src)[idx];
    uint2 h, l;
    h.x = pk(bf_hi_f(x.x), bf_hi_f(x.y));
    h.y = pk(bf_hi_f(x.z), bf_hi_f(x.w));
    l.x = pk(x.x - bf_hi_f(x.x), x.y - bf_hi_f(x.y));
    l.y = pk(x.z - bf_hi_f(x.z), x.w - bf_hi_f(x.w));
    ((uint2*)dh)[idx] = h;
    ((uint2*)dl)[idx] = l;
}

__global__ __launch_bounds__(256) void cvt_weights(const float* __restrict__ wq,
                                                   const float* __restrict__ wk,
                                                   const float* __restrict__ wv,
                                                   const float* __restrict__ wo) {
    const int z = blockIdx.y;
    const float* src = (z == 0) ? wq : (z == 1) ? wk : (z == 2) ? wv : wo;
    __nv_bfloat16* dh = g_Wh + (size_t)z * HID * HID;
    __nv_bfloat16* dl = g_Wl + (size_t)z * HID * HID;
    const int idx = blockIdx.x * 256 + threadIdx.x;
    float4 x = ((const float4*)src)[idx];
    uint2 h, l;
    h.x = pk(bf_hi_f(x.x), bf_hi_f(x.y));
    h.y = pk(bf_hi_f(x.z), bf_hi_f(x.w));
    l.x = pk(x.x - bf_hi_f(x.x), x.y - bf_hi_f(x.y));
    l.y = pk(x.z - bf_hi_f(x.z), x.w - bf_hi_f(x.w));
    ((uint2*)dh)[idx] = h;
    ((uint2*)dl)[idx] = l;
}

// ---------------------------------------------------------------------------
// mask bit-pack
// ---------------------------------------------------------------------------
__global__ __launch_bounds__(256) void pack_mask(const int* __restrict__ mask) {
    int widx = blockIdx.x * 256 + threadIdx.x;
    int q = widx >> 6;
    int w = widx & 63;
    const int4* p = (const int4*)(mask + (size_t)q * SEQ + w * 32);
    uint32_t bits = 0;
#pragma unroll
    for (int i = 0; i < 8; i++) {
        int4 m = p[i];
        bits |= (m.x != 0 ? 1u : 0u) << (4 * i + 0);
        bits |= (m.y != 0 ? 1u : 0u) << (4 * i + 1);
        bits |= (m.z != 0 ? 1u : 0u) << (4 * i + 2);
        bits |= (m.w != 0 ? 1u : 0u) << (4 * i + 3);
    }
    g_mbits[widx] = bits;
}

// ---------------------------------------------------------------------------
// bf16-split GEMM with 4-stage cp.async pipeline.
// C = A @ W^T + bias; 3 virtual passes [AhBh],[AlBh],[AhBl] over K=1024.
// CTA 128x128, BK=32, 8 warps (2m x 4n), warp tile 64x32.
// ---------------------------------------------------------------------------
#define SROW 40                       // bf16/row (32 + 8 pad), 80 B pitch
#define TILE_BYTES (128 * SROW * 2)   // 10240
#define STAGE_BYTES (2 * TILE_BYTES)  // A + B = 20480
#define NSTAGE 4
#define GEMM_SMEM (NSTAGE * STAGE_BYTES)   // 81920

template <int MODE>
__device__ __forceinline__ void gemm_body(const __nv_bfloat16* __restrict__ Ah,
                                          const __nv_bfloat16* __restrict__ Al,
                                          const __nv_bfloat16* __restrict__ Bh,
                                          const __nv_bfloat16* __restrict__ Bl,
                                          const float* __restrict__ bias,
                                          float* __restrict__ Cf,
                                          __nv_bfloat16* __restrict__ Chi,
                                          __nv_bfloat16* __restrict__ Clo) {
    extern __shared__ char dynsm[];
    const uint32_t sb = smem_u32(dynsm);

    const int tid  = threadIdx.x;
    const int lane = tid & 31;
    const int w    = tid >> 5;
    const int wm   = w >> 2;
    const int wn   = w & 3;
    const int m0   = blockIdx.x * 128;
    const int n0   = blockIdx.y * 128;

    const int lrow = tid >> 2;          // 0..63
    const int lc16 = tid & 3;           // 16B chunk in row

    float acc[4][4][4];
#pragma unroll
    for (int i = 0; i < 4; i++)
#pragma unroll
        for (int j = 0; j < 4; j++)
#pragma unroll
            for (int e = 0; e < 4; e++) acc[i][j][e] = 0.f;

    auto issue = [&](int t) {
        const int pass = t >> 5;
        const int k0   = (t & 31) * 32;
        const __nv_bfloat16* As = (pass == 1) ? Al : Ah;
        const __nv_bfloat16* Bs = (pass == 2) ? Bl : Bh;
        const uint32_t st = sb + (uint32_t)(t & (NSTAGE - 1)) * STAGE_BYTES;
        const uint32_t so = (uint32_t)(lrow * 80 + lc16 * 16);
        cp16(st + so,                         As + (size_t)(m0 + lrow) * HID + k0 + lc16 * 8);
        cp16(st + so + 64 * 80,               As + (size_t)(m0 + lrow + 64) * HID + k0 + lc16 * 8);
        cp16(st + TILE_BYTES + so,            Bs + (size_t)(n0 + lrow) * HID + k0 + lc16 * 8);
        cp16(st + TILE_BYTES + so + 64 * 80,  Bs + (size_t)(n0 + lrow + 64) * HID + k0 + lc16 * 8);
        CP_COMMIT();
    };

    issue(0); issue(1); issue(2);

    const int NT = 96;
    for (int t = 0; t < NT; t++) {
        CP_WAIT2();
        __syncthreads();
        if (t + 3 < NT) issue(t + 3);

        const uint32_t sAb = sb + (uint32_t)(t & (NSTAGE - 1)) * STAGE_BYTES;
        const uint32_t sBb = sAb + TILE_BYTES;
        uint32_t afr[4][4], bfr[4][2];
#pragma unroll
        for (int kk = 0; kk < 2; kk++) {
#pragma unroll
            for (int i = 0; i < 4; i++)
                ldsm_x4(afr[i], sAb + 2u * ((wm * 64 + 16 * i + (lane & 15)) * SROW
                                            + kk * 16 + ((lane >> 4) & 1) * 8));
#pragma unroll
            for (int j = 0; j < 4; j++)
                ldsm_x2(bfr[j], sBb + 2u * ((wn * 32 + 8 * j + (lane & 7)) * SROW
                                            + kk * 16 + ((lane >> 3) & 1) * 8));
#pragma unroll
            for (int i = 0; i < 4; i++)
#pragma unroll
                for (int j = 0; j < 4; j++) mma_bf16(acc[i][j], afr[i], bfr[j]);
        }
    }

    // epilogue
#pragma unroll
    for (int j = 0; j < 4; j++) {
        const int gn0 = n0 + wn * 32 + 8 * j + 2 * (lane & 3);
        const float b0 = __ldg(bias + gn0);
        const float b1 = __ldg(bias + gn0 + 1);
#pragma unroll
        for (int i = 0; i < 4; i++) {
            const int r0 = m0 + wm * 64 + 16 * i + (lane >> 2);
            const int r1 = r0 + 8;
            float c0 = acc[i][j][0] + b0, c1 = acc[i][j][1] + b1;
            float c2 = acc[i][j][2] + b0, c3 = acc[i][j][3] + b1;
            if (MODE == 1) {
                *(float2*)(Cf + (size_t)r0 * HID + gn0) = make_float2(c0, c1);
                *(float2*)(Cf + (size_t)r1 * HID + gn0) = make_float2(c2, c3);
            } else {
                const int head = gn0 >> 6;
                const int d    = gn0 & 63;
                size_t i0 = ((size_t)head * SEQ + r0) * DK + d;
                size_t i1 = ((size_t)head * SEQ + r1) * DK + d;
                *(uint32_t*)(Chi + i0) = pk(bf_hi_f(c0), bf_hi_f(c1));
                *(uint32_t*)(Clo + i0) = pk(c0 - bf_hi_f(c0), c1 - bf_hi_f(c1));
                *(uint32_t*)(Chi + i1) = pk(bf_hi_f(c2), bf_hi_f(c3));
                *(uint32_t*)(Clo + i1) = pk(c2 - bf_hi_f(c2), c3 - bf_hi_f(c3));
            }
        }
    }
}

__global__ __launch_bounds__(256, 2) void qkv_gemm(
    const float* __restrict__ bq, const float* __restrict__ bk,
    const float* __restrict__ bv) {
    const int z = blockIdx.z;
    const __nv_bfloat16* Ah = g_Xh + (size_t)z * SEQ * HID;
    const __nv_bfloat16* Al = g_Xl + (size_t)z * SEQ * HID;
    const __nv_bfloat16* Bh = g_Wh + (size_t)z * HID * HID;
    const __nv_bfloat16* Bl = g_Wl + (size_t)z * HID * HID;
    const float* bias = (z == 0) ? bq : (z == 1) ? bk : bv;
    __nv_bfloat16 *Ch, *Cl;
    if (z == 0)      { Ch = g_Qhh; Cl = g_Qll; }
    else if (z == 1) { Ch = g_Khh; Cl = g_Kll; }
    else             { Ch = g_Vhh; Cl = g_Vll; }
    gemm_body<0>(Ah, Al, Bh, Bl, bias, nullptr, Ch, Cl);
}

__global__ __launch_bounds__(256, 2) void out_gemm(
    const float* __restrict__ bo, float* __restrict__ out) {
    gemm_body<1>(g_Obh, g_Obl, g_Wh + (size_t)3 * HID * HID,
                 g_Wl + (size_t)3 * HID * HID, bo, out, nullptr, nullptr);
}

// ---------------------------------------------------------------------------
// Attention (as R6, epilogue now writes bf16 hi/lo Ob planes)
// ---------------------------------------------------------------------------
#define AROW 72
#define ATILE (128 * AROW)
#define ASMEM_BYTES (6 * ATILE * 2)

__global__ __launch_bounds__(256) void attn_kernel() {
    extern __shared__ __nv_bfloat16 sm[];
    __nv_bfloat16* sQh = sm;
    __nv_bfloat16* sQl = sm + ATILE;
    __nv_bfloat16* sKh = sm + 2 * ATILE;
    __nv_bfloat16* sKl = sm + 3 * ATILE;
    __nv_bfloat16* sVh = sm + 4 * ATILE;
    __nv_bfloat16* sVl = sm + 5 * ATILE;

    const int tid  = threadIdx.x;
    const int lane = tid & 31;
    const int w    = tid >> 5;
    const int head = blockIdx.y;
    const int q0   = blockIdx.x * 128;

    const uint32_t bQh = smem_u32(sQh), bQl = smem_u32(sQl);
    const uint32_t bKh = smem_u32(sKh), bKl = smem_u32(sKl);
    const uint32_t bVh = smem_u32(sVh), bVl = smem_u32(sVl);

    const size_t hbase = (size_t)head * SEQ * DK;

#pragma unroll
    for (int q = 0; q < 4; q++) {
        int idx = tid + q * 256;
        int r   = idx >> 3;
        int cc  = (idx & 7) * 8;
        *(uint4*)(sQh + r * AROW + cc) = *(const uint4*)(g_Qhh + hbase + (size_t)(q0 + r) * DK + cc);
        *(uint4*)(sQl + r * AROW + cc) = *(const uint4*)(g_Qll + hbase + (size_t)(q0 + r) * DK + cc);
    }

    float oacc[8][4];
#pragma unroll
    for (int j = 0; j < 8; j++)
#pragma unroll
        for (int e = 0; e < 4; e++) oacc[j][e] = 0.f;
    float mrow[2] = {-1e30f, -1e30f};
    float lrow[2] = {0.f, 0.f};

    const int row0g = q0 + 16 * w + (lane >> 2);
    const int row1g = row0g + 8;

    for (int kb = 0; kb < SEQ / 128; kb++) {
        __syncthreads();
#pragma unroll
        for (int q = 0; q < 4; q++) {
            int idx = tid + q * 256;
            int r   = idx >> 3;
            int cc  = (idx & 7) * 8;
            size_t g = hbase + (size_t)(kb * 128 + r) * DK + cc;
            *(uint4*)(sKh + r * AROW + cc) = *(const uint4*)(g_Khh + g);
            *(uint4*)(sKl + r * AROW + cc) = *(const uint4*)(g_Kll + g);
            *(uint4*)(sVh + r * AROW + cc) = *(const uint4*)(g_Vhh + g);
            *(uint4*)(sVl + r * AROW + cc) = *(const uint4*)(g_Vll + g);
        }
        __syncthreads();

        float sacc[16][4];
#pragma unroll
        for (int j = 0; j < 16; j++)
#pragma unroll
            for (int e = 0; e < 4; e++) sacc[j][e] = 0.f;

        const uint32_t a_off = 2u * ((16 * w + (lane & 15)) * AROW + ((lane >> 4) & 1) * 8);
        const uint32_t b_roff = 2u * ((lane & 7) * AROW + ((lane >> 3) & 1) * 8);

#pragma unroll
        for (int kk = 0; kk < 4; kk++) {
            uint32_t qh[4], ql[4];
            ldsm_x4(qh, bQh + a_off + 2u * kk * 16);
            ldsm_x4(ql, bQl + a_off + 2u * kk * 16);
#pragma unroll
            for (int j = 0; j < 16; j++) {
                uint32_t kf[2];
                ldsm_x2(kf, bKh + b_roff + 2u * (8 * j * AROW + kk * 16));
                mma_bf16(sacc[j], qh, kf);
                mma_bf16(sacc[j], ql, kf);
            }
#pragma unroll
            for (int j = 0; j < 16; j++) {
                uint32_t kf[2];
                ldsm_x2(kf, bKl + b_roff + 2u * (8 * j * AROW + kk * 16));
                mma_bf16(sacc[j], qh, kf);
            }
        }

        uint32_t mw0[4], mw1[4];
#pragma unroll
        for (int i = 0; i < 4; i++) {
            mw0[i] = g_mbits[(size_t)row0g * 64 + kb * 4 + i];
            mw1[i] = g_mbits[(size_t)row1g * 64 + kb * 4 + i];
        }
#pragma unroll
        for (int j = 0; j < 16; j++) {
            int kl = 8 * j + 2 * (lane & 3);
            uint32_t w0 = mw0[kl >> 5], w1 = mw1[kl >> 5];
            int b = kl & 31;
            sacc[j][0] = ((w0 >> b) & 1)       ? sacc[j][0] * 0.125f : 0.f;
            sacc[j][1] = ((w0 >> (b + 1)) & 1) ? sacc[j][1] * 0.125f : 0.f;
            sacc[j][2] = ((w1 >> b) & 1)       ? sacc[j][2] * 0.125f : 0.f;
            sacc[j][3] = ((w1 >> (b + 1)) & 1) ? sacc[j][3] * 0.125f : 0.f;
        }

        float mx0 = -1e30f, mx1 = -1e30f;
#pragma unroll
        for (int j = 0; j < 16; j++) {
            mx0 = fmaxf(mx0, fmaxf(sacc[j][0], sacc[j][1]));
            mx1 = fmaxf(mx1, fmaxf(sacc[j][2], sacc[j][3]));
        }
        mx0 = fmaxf(mx0, __shfl_xor_sync(0xffffffffu, mx0, 1, 4));
        mx0 = fmaxf(mx0, __shfl_xor_sync(0xffffffffu, mx0, 2, 4));
        mx1 = fmaxf(mx1, __shfl_xor_sync(0xffffffffu, mx1, 1, 4));
        mx1 = fmaxf(mx1, __shfl_xor_sync(0xffffffffu, mx1, 2, 4));
        const float mn0 = fmaxf(mrow[0], mx0);
        const float mn1 = fmaxf(mrow[1], mx1);
        float s0 = 0.f, s1 = 0.f;
#pragma unroll
        for (int j = 0; j < 16; j++) {
            sacc[j][0] = __expf(sacc[j][0] - mn0); s0 += sacc[j][0];
            sacc[j][1] = __expf(sacc[j][1] - mn0); s0 += sacc[j][1];
            sacc[j][2] = __expf(sacc[j][2] - mn1); s1 += sacc[j][2];
            sacc[j][3] = __expf(sacc[j][3] - mn1); s1 += sacc[j][3];
        }
        s0 += __shfl_xor_sync(0xffffffffu, s0, 1, 4);
        s0 += __shfl_xor_sync(0xffffffffu, s0, 2, 4);
        s1 += __shfl_xor_sync(0xffffffffu, s1, 1, 4);
        s1 += __shfl_xor_sync(0xffffffffu, s1, 2, 4);
        const float c0 = __expf(mrow[0] - mn0);
        const float c1 = __expf(mrow[1] - mn1);
        lrow[0] = lrow[0] * c0 + s0; mrow[0] = mn0;
        lrow[1] = lrow[1] * c1 + s1; mrow[1] = mn1;
#pragma unroll
        for (int j = 0; j < 8; j++) {
            oacc[j][0] *= c0; oacc[j][1] *= c0;
            oacc[j][2] *= c1; oacc[j][3] *= c1;
        }

        const uint32_t v_coff = 2u * ((lane & 15) * AROW);
#pragma unroll
        for (int kk = 0; kk < 8; kk++) {
            uint32_t ah[4], al[4];
            float p00 = sacc[2 * kk][0],     p01 = sacc[2 * kk][1];
            float p02 = sacc[2 * kk][2],     p03 = sacc[2 * kk][3];
            float p10 = sacc[2 * kk + 1][0], p11 = sacc[2 * kk + 1][1];
            float p12 = sacc[2 * kk + 1][2], p13 = sacc[2 * kk + 1][3];
            ah[0] = pk(p00, p01); ah[1] = pk(p02, p03);
            ah[2] = pk(p10, p11); ah[3] = pk(p12, p13);
            al[0] = pk(p00 - bf_hi_f(p00), p01 - bf_hi_f(p01));
            al[1] = pk(p02 - bf_hi_f(p02), p03 - bf_hi_f(p03));
            al[2] = pk(p10 - bf_hi_f(p10), p11 - bf_hi_f(p11));
            al[3] = pk(p12 - bf_hi_f(p12), p13 - bf_hi_f(p13));
            const uint32_t vrow = 2u * (16 * kk * AROW) + v_coff;
#pragma unroll
            for (int j = 0; j < 8; j++) {
                uint32_t vf[2];
                ldsm_x2t(vf, bVh + vrow + 2u * (j * 8));
                mma_bf16(oacc[j], ah, vf);
                mma_bf16(oacc[j], al, vf);
            }
#pragma unroll
            for (int j = 0; j < 8; j++) {
                uint32_t vf[2];
                ldsm_x2t(vf, bVl + vrow + 2u * (j * 8));
                mma_bf16(oacc[j], ah, vf);
            }
        }
    }

    // epilogue: normalize, write bf16 hi/lo planes of Ob
    const float inv0 = 1.f / lrow[0];
    const float inv1 = 1.f / lrow[1];
#pragma unroll
    for (int j = 0; j < 8; j++) {
        const int col = head * DK + 8 * j + 2 * (lane & 3);
        float o0 = oacc[j][0] * inv0, o1 = oacc[j][1] * inv0;
        float o2 = oacc[j][2] * inv1, o3 = oacc[j][3] * inv1;
        *(uint32_t*)(g_Obh + (size_t)row0g * HID + col) = pk(bf_hi_f(o0), bf_hi_f(o1));
        *(uint32_t*)(g_Obl + (size_t)row0g * HID + col) = pk(o0 - bf_hi_f(o0), o1 - bf_hi_f(o1));
        *(uint32_t*)(g_Obh + (size_t)row1g * HID + col) = pk(bf_hi_f(o2), bf_hi_f(o3));
        *(uint32_t*)(g_Obl + (size_t)row1g * HID + col) = pk(o2 - bf_hi_f(o2), o3 - bf_hi_f(o3));
    }
}

// ---------------------------------------------------------------------------
extern "C" void kernel_launch(void* const* d_in, const int* in_sizes, int n_in,
                              void* d_out, int out_size) {
    const float* q    = (const float*)d_in[0];
    const float* k    = (const float*)d_in[1];
    const float* v    = (const float*)d_in[2];
    const int*   mask = (const int*)  d_in[3];
    const float* Wq   = (const float*)d_in[4];
    const float* bq   = (const float*)d_in[5];
    const float* Wk   = (const float*)d_in[6];
    const float* bk   = (const float*)d_in[7];
    const float* Wv   = (const float*)d_in[8];
    const float* bv   = (const float*)d_in[9];
    const float* Wo   = (const float*)d_in[10];
    const float* bo   = (const float*)d_in[11];
    float* out = (float*)d_out;

    static bool attr_set = false;
    if (!attr_set) {
        cudaFuncSetAttribute(attn_kernel, cudaFuncAttributeMaxDynamicSharedMemorySize,
                             ASMEM_BYTES);
        cudaFuncSetAttribute(qkv_gemm, cudaFuncAttributeMaxDynamicSharedMemorySize,
                             GEMM_SMEM);
        cudaFuncSetAttribute(out_gemm, cudaFuncAttributeMaxDynamicSharedMemorySize,
                             GEMM_SMEM);
        attr_set = true;
    }

    cvt_inputs<<<dim3(SEQ * HID / 4 / 256, 3), 256>>>(q, k, v);
    cvt_weights<<<dim3(HID * HID / 4 / 256, 4), 256>>>(Wq, Wk, Wv, Wo);
    pack_mask<<<SEQ * (SEQ / 32) / 256, 256>>>(mask);
    qkv_gemm<<<dim3(SEQ / 128, HID / 128, 3), 256, GEMM_SMEM>>>(bq, bk, bv);
    attn_kernel<<<dim3(SEQ / 128, NHEAD), 256, ASMEM_BYTES>>>();
    out_gemm<<<dim3(SEQ / 128, HID / 128), 256, GEMM_SMEM>>>(bo, out);
}